// round 14
// baseline (speedup 1.0000x reference)
#include <cuda_runtime.h>
#include <cuda_bf16.h>
#include <cstdint>

#define B_ 2
#define L_ 2048
#define D_ 1024
#define H_ 16
#define DH_ 64
#define M_ (B_*L_)
#define OUT_ELEMS (B_*L_*D_)

// -------- scratch (static device arrays; no cudaMalloc allowed) --------
__device__ float g_sal[B_*H_*L_];
__device__ __nv_bfloat16 g_Ahi[M_*D_];
__device__ __nv_bfloat16 g_Alo[M_*D_];
__device__ __nv_bfloat16 g_Whi[4][D_*D_];
__device__ __nv_bfloat16 g_Wlo[4][D_*D_];
__device__ __nv_bfloat16 g_Qh[B_*H_*L_*DH_];
__device__ __nv_bfloat16 g_Ql[B_*H_*L_*DH_];
__device__ __nv_bfloat16 g_Kh[B_*H_*L_*DH_];
__device__ __nv_bfloat16 g_Kl[B_*H_*L_*DH_];
__device__ __nv_bfloat16 g_Vh[B_*H_*L_*DH_];
__device__ __nv_bfloat16 g_Vl[B_*H_*L_*DH_];

__device__ __forceinline__ uint32_t smem_u32(const void* p) {
    uint32_t a;
    asm("{ .reg .u64 t; cvta.to.shared.u64 t, %1; cvt.u32.u64 %0, t; }"
        : "=r"(a) : "l"(p));
    return a;
}

// -------- cp.async helpers --------
#define CP_ASYNC16(dst, src) \
    asm volatile("cp.async.cg.shared.global [%0], [%1], 16;" \
        :: "r"(dst), "l"(src))
#define CP_COMMIT() asm volatile("cp.async.commit_group;")
#define CP_WAIT1()  asm volatile("cp.async.wait_group 1;")
#define CP_WAIT0()  asm volatile("cp.async.wait_group 0;")

// ---------------- mma/ldmatrix primitives ----------------
__device__ __forceinline__ void ldm_x4(uint32_t* r, uint32_t addr) {
    asm volatile("ldmatrix.sync.aligned.m8n8.x4.shared.b16 {%0,%1,%2,%3}, [%4];"
        : "=r"(r[0]), "=r"(r[1]), "=r"(r[2]), "=r"(r[3]) : "r"(addr));
}
__device__ __forceinline__ void ldm_x2(uint32_t* r, uint32_t addr) {
    asm volatile("ldmatrix.sync.aligned.m8n8.x2.shared.b16 {%0,%1}, [%2];"
        : "=r"(r[0]), "=r"(r[1]) : "r"(addr));
}
__device__ __forceinline__ void ldm_x2_t(uint32_t* r, uint32_t addr) {
    asm volatile("ldmatrix.sync.aligned.m8n8.x2.trans.shared.b16 {%0,%1}, [%2];"
        : "=r"(r[0]), "=r"(r[1]) : "r"(addr));
}
__device__ __forceinline__ void mma16816(float* c, const uint32_t* a, const uint32_t* b) {
    asm volatile(
        "mma.sync.aligned.m16n8k16.row.col.f32.bf16.bf16.f32 "
        "{%0,%1,%2,%3}, {%4,%5,%6,%7}, {%8,%9}, {%0,%1,%2,%3};"
        : "+f"(c[0]), "+f"(c[1]), "+f"(c[2]), "+f"(c[3])
        : "r"(a[0]), "r"(a[1]), "r"(a[2]), "r"(a[3]), "r"(b[0]), "r"(b[1]));
}

// ============================================================================
// fp32 -> bf16 hi/lo split (vectorized)
// ============================================================================
__global__ void __launch_bounds__(256) cvt_split(
    const float* __restrict__ x, __nv_bfloat16* __restrict__ hi,
    __nv_bfloat16* __restrict__ lo, int n4)
{
    int i = blockIdx.x * blockDim.x + threadIdx.x;
    if (i >= n4) return;
    float4 v = ((const float4*)x)[i];
    __nv_bfloat16 h0 = __float2bfloat16(v.x);
    __nv_bfloat16 h1 = __float2bfloat16(v.y);
    __nv_bfloat16 h2 = __float2bfloat16(v.z);
    __nv_bfloat16 h3 = __float2bfloat16(v.w);
    __nv_bfloat162* hp = (__nv_bfloat162*)hi;
    __nv_bfloat162* lp = (__nv_bfloat162*)lo;
    hp[2 * i]     = __nv_bfloat162(h0, h1);
    hp[2 * i + 1] = __nv_bfloat162(h2, h3);
    lp[2 * i]     = __nv_bfloat162(__float2bfloat16(v.x - __bfloat162float(h0)),
                                   __float2bfloat16(v.y - __bfloat162float(h1)));
    lp[2 * i + 1] = __nv_bfloat162(__float2bfloat16(v.z - __bfloat162float(h2)),
                                   __float2bfloat16(v.w - __bfloat162float(h3)));
}

// 4 weights in one launch: grid.y selects the matrix
__global__ void __launch_bounds__(256) cvt_split_w(
    const float* __restrict__ w0, const float* __restrict__ w1,
    const float* __restrict__ w2, const float* __restrict__ w3,
    __nv_bfloat16* __restrict__ hi, __nv_bfloat16* __restrict__ lo)
{
    const int wsel = blockIdx.y;
    const float* x = (wsel == 0) ? w0 : (wsel == 1) ? w1 : (wsel == 2) ? w2 : w3;
    int i = blockIdx.x * blockDim.x + threadIdx.x;
    float4 v = ((const float4*)x)[i];
    size_t off = (size_t)wsel * (D_ * D_ / 2) + 2 * (size_t)i;
    __nv_bfloat16 h0 = __float2bfloat16(v.x);
    __nv_bfloat16 h1 = __float2bfloat16(v.y);
    __nv_bfloat16 h2 = __float2bfloat16(v.z);
    __nv_bfloat16 h3 = __float2bfloat16(v.w);
    ((__nv_bfloat162*)hi)[off]     = __nv_bfloat162(h0, h1);
    ((__nv_bfloat162*)hi)[off + 1] = __nv_bfloat162(h2, h3);
    ((__nv_bfloat162*)lo)[off]     = __nv_bfloat162(
        __float2bfloat16(v.x - __bfloat162float(h0)),
        __float2bfloat16(v.y - __bfloat162float(h1)));
    ((__nv_bfloat162*)lo)[off + 1] = __nv_bfloat162(
        __float2bfloat16(v.z - __bfloat162float(h2)),
        __float2bfloat16(v.w - __bfloat162float(h3)));
}

// ============================================================================
// mma.sync bf16x3 GEMM, cp.async double-buffered; 2 CTAs/SM.
// Inner loop TERM-MAJOR: same-accumulator MMAs are 4 apart (latency hiding).
// qkv=1: grid.z selects W slice + bias + headed dest (Q/K/V). qkv=0: Wo->C.
// ============================================================================
#define TSTRIDE 40
#define GSTAGE 40960
#define GEMM_SMEM (2 * GSTAGE)

__global__ void __launch_bounds__(256, 2) mma_gemm_bf16x3(
    const __nv_bfloat16* __restrict__ Ah, const __nv_bfloat16* __restrict__ Al,
    const __nv_bfloat16* __restrict__ Wh0, const __nv_bfloat16* __restrict__ Wl0,
    const float* __restrict__ b0, const float* __restrict__ b1,
    const float* __restrict__ b2,
    float* __restrict__ C,
    __nv_bfloat16* __restrict__ Qh, __nv_bfloat16* __restrict__ Ql,
    __nv_bfloat16* __restrict__ Kh, __nv_bfloat16* __restrict__ Kl,
    __nv_bfloat16* __restrict__ Vh, __nv_bfloat16* __restrict__ Vl,
    int qkv)
{
    extern __shared__ __align__(128) char smg[];
    const uint32_t smb = smem_u32(smg);

    const int tid = threadIdx.x;
    const int wid = tid >> 5;
    const int lane = tid & 31;
    const int wm = (wid & 1) * 64;
    const int wn = (wid >> 1) * 32;
    const int m0 = blockIdx.y * 128;
    const int n0 = blockIdx.x * 128;
    const int z = qkv ? blockIdx.z : 3;

    const __nv_bfloat16* Bh = Wh0 + (size_t)z * D_ * D_;
    const __nv_bfloat16* Bl = Wl0 + (size_t)z * D_ * D_;
    const float* bias = qkv ? (z == 0 ? b0 : (z == 1 ? b1 : b2)) : b0;
    __nv_bfloat16* Ch = qkv ? (z == 0 ? Qh : (z == 1 ? Kh : Vh)) : nullptr;
    __nv_bfloat16* Cl = qkv ? (z == 0 ? Ql : (z == 1 ? Kl : Vl)) : nullptr;

    float c[4][4][4];
#pragma unroll
    for (int i = 0; i < 4; ++i)
#pragma unroll
        for (int j = 0; j < 4; ++j)
#pragma unroll
            for (int r = 0; r < 4; ++r) c[i][j][r] = 0.f;

    auto issue = [&](int i, int st) {
        const int k0 = i * 32;
        const uint32_t sb = smb + st * GSTAGE;
#pragma unroll
        for (int t = 0; t < 2; ++t) {
            int idx = t * 256 + tid;
            int row = idx >> 2, sub = idx & 3;
            uint32_t off = (uint32_t)(row * TSTRIDE + sub * 8) * 2;
            size_t ga = (size_t)(m0 + row) * D_ + k0 + sub * 8;
            size_t gb = (size_t)(n0 + row) * D_ + k0 + sub * 8;
            CP_ASYNC16(sb + off,         Ah + ga);
            CP_ASYNC16(sb + 10240 + off, Al + ga);
            CP_ASYNC16(sb + 20480 + off, Bh + gb);
            CP_ASYNC16(sb + 30720 + off, Bl + gb);
        }
    };

    const int arow = lane & 15, acol = (lane >> 4) << 3;
    const int brow = lane & 7,  bcol = ((lane >> 3) & 1) << 3;

    issue(0, 0); CP_COMMIT();
    issue(1, 1); CP_COMMIT();

    for (int i = 0; i < 32; ++i) {
        if (i < 31) CP_WAIT1(); else CP_WAIT0();
        __syncthreads();
        const uint32_t aB = smb + (i & 1) * GSTAGE;

#pragma unroll
        for (int ks = 0; ks < 2; ++ks) {
            const int kk = ks * 16;
            uint32_t ah[4][4], al[4][4];
#pragma unroll
            for (int mt = 0; mt < 4; ++mt) {
                uint32_t off = (uint32_t)((wm + mt * 16 + arow) * TSTRIDE + kk + acol) * 2;
                ldm_x4(ah[mt], aB + off);
                ldm_x4(al[mt], aB + 10240 + off);
            }
#pragma unroll
            for (int nt = 0; nt < 4; ++nt) {
                uint32_t boff = (uint32_t)((wn + nt * 8 + brow) * TSTRIDE + kk + bcol) * 2;
                uint32_t bh[2], bl[2];
                ldm_x2(bh, aB + 20480 + boff);
                ldm_x2(bl, aB + 30720 + boff);
                // term-major: same-accumulator MMAs are 4 apart
#pragma unroll
                for (int mt = 0; mt < 4; ++mt) mma16816(c[mt][nt], ah[mt], bh);
#pragma unroll
                for (int mt = 0; mt < 4; ++mt) mma16816(c[mt][nt], ah[mt], bl);
#pragma unroll
                for (int mt = 0; mt < 4; ++mt) mma16816(c[mt][nt], al[mt], bh);
            }
        }
        __syncthreads();
        if (i + 2 < 32) { issue(i + 2, i & 1); CP_COMMIT(); }
    }

    const int rl = lane >> 2;
    const int cl = (lane & 3) * 2;
#pragma unroll
    for (int mt = 0; mt < 4; ++mt) {
#pragma unroll
        for (int half = 0; half < 2; ++half) {
            int m = m0 + wm + mt * 16 + rl + half * 8;
            int b = m >> 11, l = m & 2047;
#pragma unroll
            for (int nt = 0; nt < 4; ++nt) {
                int n = n0 + wn + nt * 8 + cl;
                float v0 = c[mt][nt][half * 2 + 0] + bias[n];
                float v1 = c[mt][nt][half * 2 + 1] + bias[n + 1];
                if (!qkv) {
                    *(float2*)(C + (size_t)m * D_ + n) = make_float2(v0, v1);
                } else {
                    int h = n >> 6, dh = n & 63;
                    size_t off = (size_t)(((b << 4) + h) * 2048 + l) * 64 + dh;
                    __nv_bfloat16 h0 = __float2bfloat16(v0);
                    __nv_bfloat16 h1 = __float2bfloat16(v1);
                    *(__nv_bfloat162*)(Ch + off) = __nv_bfloat162(h0, h1);
                    *(__nv_bfloat162*)(Cl + off) = __nv_bfloat162(
                        __float2bfloat16(v0 - __bfloat162float(h0)),
                        __float2bfloat16(v1 - __bfloat162float(h1)));
                }
            }
        }
    }
}

// ============================================================================
// Saliency Conv1d(D->H, k=3, pad=1): sal[b,h,l]
// ============================================================================
#define CONV_SMEM (18 * 1028 * 4)
__global__ void __launch_bounds__(256) conv_sal_kernel(
    const float* __restrict__ src, const float* __restrict__ cw,
    const float* __restrict__ cb, float* __restrict__ sal)
{
    extern __shared__ float ss[];
    const int bid = blockIdx.x;
    const int b = bid >> 7, lt = bid & 127;
    const int l0 = lt * 16;
    const int tid = threadIdx.x;

#pragma unroll
    for (int it = 0; it < 18; ++it) {
        int idx = it * 256 + tid;
        int row = idx >> 8;
        int c4 = idx & 255;
        int gl = l0 + row - 1;
        float4 v = make_float4(0.f, 0.f, 0.f, 0.f);
        if (gl >= 0 && gl < L_)
            v = *(const float4*)(src + ((size_t)b * L_ + gl) * D_ + c4 * 4);
        *(float4*)(ss + row * 1028 + c4 * 4) = v;
    }
    __syncthreads();

    const int h = tid >> 4, li = tid & 15;
    const float* wp = cw + (size_t)h * D_ * 3;
    float acc = 0.f;
#pragma unroll 4
    for (int d = 0; d < D_; ++d) {
        float w0 = wp[d * 3 + 0], w1 = wp[d * 3 + 1], w2 = wp[d * 3 + 2];
        acc = fmaf(ss[(li + 0) * 1028 + d], w0, acc);
        acc = fmaf(ss[(li + 1) * 1028 + d], w1, acc);
        acc = fmaf(ss[(li + 2) * 1028 + d], w2, acc);
    }
    sal[(size_t)(b * H_ + h) * L_ + l0 + li] = acc + cb[h];
}

// ============================================================================
// Fused tensor-core attention, 512 threads (16 warps):
//  Phase1: per-warp K streaming (no CTA barriers); 3 per-term accumulators
//          (independent HMMA chains); S = exp(...) via MUFU -> split Ph/Pl.
//  Phase2: CTA-shared V staging; 3 persistent accumulators across tiles.
// SMEM layout identical to R11.
// ============================================================================
#define PH_PITCH 2056
#define PL_OFF  65792
#define KV_OFF  131584
#define KV_STG  36864
#define SL_WARP 4608
#define SL_STG  2304
#define SAL_OFF 205312
#define RED_OFF 205312
#define Q_OFF   213504
#define SUM_OFF 218112
#define INV_OFF 219136
#define ATTN_SMEM 219200

__global__ void __launch_bounds__(512) attn_kernel(
    const __nv_bfloat16* __restrict__ Qh, const __nv_bfloat16* __restrict__ Ql,
    const __nv_bfloat16* __restrict__ Kh, const __nv_bfloat16* __restrict__ Kl,
    const __nv_bfloat16* __restrict__ Vh, const __nv_bfloat16* __restrict__ Vl,
    const float* __restrict__ sal,
    __nv_bfloat16* __restrict__ ctxh, __nv_bfloat16* __restrict__ ctxl,
    float* __restrict__ attn)
{
    extern __shared__ __align__(128) char smem[];
    __nv_bfloat16* sPh = (__nv_bfloat16*)smem;
    __nv_bfloat16* sPl = (__nv_bfloat16*)(smem + PL_OFF);
    float* sSal = (float*)(smem + SAL_OFF);
    float* sSum = (float*)(smem + SUM_OFF);
    float* sInv = (float*)(smem + INV_OFF);
    const uint32_t smb = smem_u32(smem);
    const uint32_t phB = smb;
    const uint32_t plB = smb + PL_OFF;

    const int tid = threadIdx.x;
    const int wid = tid >> 5;
    const int lane = tid & 31;
    const int q0 = blockIdx.x * 16;
    const int bh = blockIdx.y;
    const size_t base = (size_t)bh * (L_ * DH_);
    const uint32_t wsl = smb + KV_OFF + wid * SL_WARP;

    // stage sal row + Q tile
    {
        const float4* gs = (const float4*)(sal + (size_t)bh * L_);
        ((float4*)sSal)[tid] = gs[tid];
        if (tid < 256) {
            int idx = tid & 127;
            int r = idx >> 3, s = idx & 7;
            const uint4* gq = (const uint4*)((tid < 128 ? Qh : Ql) + base + (size_t)q0 * DH_);
            __nv_bfloat16* dq = (__nv_bfloat16*)(smem + Q_OFF) + (tid < 128 ? 0 : 16 * 72);
            *(uint4*)(dq + r * 72 + s * 8) = gq[idx];
        }
    }
    __syncthreads();

    // preload Q fragments (m16 x k64, hi + lo)
    const int arow = lane & 15, acol = (lane >> 4) << 3;
    const int brow = lane & 7;
    const uint32_t bcol16 = ((lane >> 3) & 1) << 4;
    uint32_t fQh[4][4], fQl[4][4];
    {
        const uint32_t qhB = smb + Q_OFF;
        const uint32_t qlB = qhB + 16 * 72 * 2;
#pragma unroll
        for (int ks = 0; ks < 4; ++ks) {
            uint32_t off = (uint32_t)(arow * 72 + ks * 16 + acol) * 2;
            ldm_x4(fQh[ks], qhB + off);
            ldm_x4(fQl[ks], qlB + off);
        }
    }

    // per-warp K slice: 8 rows x 64 bf16 (pitch 144B), hi @0, lo @1152
    auto issueK = [&](int kt, int st) {
        const uint32_t sb = wsl + st * SL_STG;
        const size_t gk = base + (size_t)(kt * 128 + wid * 8) * DH_;
#pragma unroll
        for (int j = 0; j < 2; ++j) {
            int id = lane + 32 * j;
            int row = id >> 3, seg = id & 7;
            uint32_t off = (uint32_t)(row * 144 + seg * 16);
            CP_ASYNC16(sb + off,        Kh + gk + (size_t)row * DH_ + seg * 8);
            CP_ASYNC16(sb + 1152 + off, Kl + gk + (size_t)row * DH_ + seg * 8);
        }
    };
    // CTA-shared V stage (phase 2)
    auto issueV = [&](int t128, int st) {
        const uint32_t sb = smb + KV_OFF + st * KV_STG;
        const __nv_bfloat16* ph = Vh + base + (size_t)t128 * 128 * DH_;
        const __nv_bfloat16* pl = Vl + base + (size_t)t128 * 128 * DH_;
#pragma unroll
        for (int t = 0; t < 2; ++t) {
            int idx = t * 512 + tid;
            int r = idx >> 3, s = idx & 7;
            uint32_t off = (uint32_t)(r * 72 + s * 8) * 2;
            CP_ASYNC16(sb + off,         ph + (size_t)r * DH_ + s * 8);
            CP_ASYNC16(sb + 18432 + off, pl + (size_t)r * DH_ + s * 8);
        }
    };

    // ---- Phase 1: per-warp streaming, 3 independent accumulator chains ----
    issueK(0, 0); CP_COMMIT();
    issueK(1, 1); CP_COMMIT();

    float sum_lo = 0.f, sum_hi = 0.f;
    const int row4 = lane >> 2;
    for (int kt = 0; kt < 16; ++kt) {
        if (kt < 15) CP_WAIT1(); else CP_WAIT0();
        __syncwarp();
        const uint32_t kb = wsl + (kt & 1) * SL_STG;

        float cA[4] = {0.f, 0.f, 0.f, 0.f};
        float cB[4] = {0.f, 0.f, 0.f, 0.f};
        float cC[4] = {0.f, 0.f, 0.f, 0.f};
        uint32_t bo = kb + (uint32_t)(brow * 144) + bcol16;
#pragma unroll
        for (int ks = 0; ks < 4; ++ks) {
            uint32_t bhf[2], blf[2];
            ldm_x2(bhf, bo + ks * 32);
            ldm_x2(blf, bo + 1152 + ks * 32);
            mma16816(cA, fQh[ks], bhf);
            mma16816(cB, fQl[ks], bhf);
            mma16816(cC, fQh[ks], blf);
        }
        if (kt + 2 < 16) { issueK(kt + 2, kt & 1); CP_COMMIT(); }

        float c0 = cA[0] + cB[0] + cC[0];
        float c1 = cA[1] + cB[1] + cC[1];
        float c2 = cA[2] + cB[2] + cC[2];
        float c3 = cA[3] + cB[3] + cC[3];

        int col = kt * 128 + wid * 8 + (lane & 3) * 2;
        float s0 = sSal[col], s1 = sSal[col + 1];
        float e0 = __expf(fmaf(c0, 0.125f, s0));
        float e1 = __expf(fmaf(c1, 0.125f, s1));
        float e2 = __expf(fmaf(c2, 0.125f, s0));
        float e3 = __expf(fmaf(c3, 0.125f, s1));
        __nv_bfloat16 h0 = __float2bfloat16(e0);
        __nv_bfloat16 h1 = __float2bfloat16(e1);
        __nv_bfloat16 h2 = __float2bfloat16(e2);
        __nv_bfloat16 h3 = __float2bfloat16(e3);
        *(__nv_bfloat162*)(sPh + row4 * PH_PITCH + col) = __nv_bfloat162(h0, h1);
        *(__nv_bfloat162*)(sPl + row4 * PH_PITCH + col) = __nv_bfloat162(
            __float2bfloat16(e0 - __bfloat162float(h0)),
            __float2bfloat16(e1 - __bfloat162float(h1)));
        *(__nv_bfloat162*)(sPh + (row4 + 8) * PH_PITCH + col) = __nv_bfloat162(h2, h3);
        *(__nv_bfloat162*)(sPl + (row4 + 8) * PH_PITCH + col) = __nv_bfloat162(
            __float2bfloat16(e2 - __bfloat162float(h2)),
            __float2bfloat16(e3 - __bfloat162float(h3)));
        sum_lo += e0 + e1;
        sum_hi += e2 + e3;
    }

    // ---- row-sum reduction (phase boundary) ----
    sum_lo += __shfl_xor_sync(0xffffffffu, sum_lo, 1);
    sum_lo += __shfl_xor_sync(0xffffffffu, sum_lo, 2);
    sum_hi += __shfl_xor_sync(0xffffffffu, sum_hi, 1);
    sum_hi += __shfl_xor_sync(0xffffffffu, sum_hi, 2);
    if ((lane & 3) == 0) {
        sSum[row4 * 16 + wid] = sum_lo;
        sSum[(row4 + 8) * 16 + wid] = sum_hi;
    }
    __syncthreads();

    issueV(0, 0); CP_COMMIT();
    issueV(1, 1); CP_COMMIT();

    if (tid < 16) {
        float s = 0.f;
#pragma unroll
        for (int j = 0; j < 16; ++j) s += sSum[tid * 16 + j];
        sInv[tid] = 1.f / s;
    }
    __syncthreads();

    // ---- Phase 2: attn write + 3-term PV with 3 persistent accumulators ----
    const int n8p = wid & 7;
    const int kh = wid >> 3;
    float ccA[4] = {0.f, 0.f, 0.f, 0.f};
    float ccB[4] = {0.f, 0.f, 0.f, 0.f};
    float ccC[4] = {0.f, 0.f, 0.f, 0.f};

    for (int lt = 0; lt < 16; ++lt) {
        if (lt < 15) CP_WAIT1(); else CP_WAIT0();
        __syncthreads();

        // attn write: one warp per row, reconstruct (hi+lo)*inv
        {
            int row = wid;
            float inv = sInv[row];
            int c0 = lt * 128 + lane * 4;
            __nv_bfloat162 a0 = *(const __nv_bfloat162*)(sPh + row * PH_PITCH + c0);
            __nv_bfloat162 a1 = *(const __nv_bfloat162*)(sPh + row * PH_PITCH + c0 + 2);
            __nv_bfloat162 b0 = *(const __nv_bfloat162*)(sPl + row * PH_PITCH + c0);
            __nv_bfloat162 b1 = *(const __nv_bfloat162*)(sPl + row * PH_PITCH + c0 + 2);
            float4 v;
            v.x = (__bfloat162float(a0.x) + __bfloat162float(b0.x)) * inv;
            v.y = (__bfloat162float(a0.y) + __bfloat162float(b0.y)) * inv;
            v.z = (__bfloat162float(a1.x) + __bfloat162float(b1.x)) * inv;
            v.w = (__bfloat162float(a1.y) + __bfloat162float(b1.y)) * inv;
            *(float4*)(attn + ((size_t)bh * L_ + q0 + row) * L_ + c0) = v;
        }

        const uint32_t vb = smb + KV_OFF + (lt & 1) * KV_STG;
#pragma unroll
        for (int ksl = 0; ksl < 4; ++ksl) {
            int ks = kh * 4 + ksl;
            int kp = lt * 128 + ks * 16;
            uint32_t fH[4], fL[4];
            uint32_t ao = (uint32_t)(arow * PH_PITCH + kp + acol) * 2;
            ldm_x4(fH, phB + ao);
            ldm_x4(fL, plB + ao);
            uint32_t vo = vb + (uint32_t)((ks * 16 + (lane & 15)) * 72 + n8p * 8) * 2;
            uint32_t fVh[2], fVl[2];
            ldm_x2_t(fVh, vo);
            ldm_x2_t(fVl, vo + 18432);
            mma16816(ccA, fH, fVh);
            mma16816(ccB, fH, fVl);
            mma16816(ccC, fL, fVh);
        }
        __syncthreads();
        if (lt + 2 < 16) { issueV(lt + 2, lt & 1); CP_COMMIT(); }
    }

    float cc[4];
#pragma unroll
    for (int r = 0; r < 4; ++r) cc[r] = ccA[r] + ccB[r] + ccC[r];

    // ---- reduce ctx partials across warp pairs, write split bf16 ----
    float* red = (float*)(smem + RED_OFF);
    *(float4*)(red + wid * 128 + lane * 4) = make_float4(cc[0], cc[1], cc[2], cc[3]);
    __syncthreads();
    if (wid < 8) {
        float4 p = *(const float4*)(red + wid * 128 + lane * 4);
        float4 q = *(const float4*)(red + (wid + 8) * 128 + lane * 4);
        float v[4] = {p.x + q.x, p.y + q.y, p.z + q.z, p.w + q.w};
        int row = lane >> 2;
        int colp = (lane & 3) * 2;
        int b = bh >> 4, h = bh & 15;
        int n = h * 64 + wid * 8 + colp;
#pragma unroll
        for (int half = 0; half < 2; ++half) {
            int r = row + half * 8;
            float inv = sInv[r];
            int m = b * 2048 + q0 + r;
            float v0 = v[half * 2 + 0] * inv, v1 = v[half * 2 + 1] * inv;
            __nv_bfloat16 h0 = __float2bfloat16(v0);
            __nv_bfloat16 h1 = __float2bfloat16(v1);
            *(__nv_bfloat162*)(ctxh + (size_t)m * D_ + n) = __nv_bfloat162(h0, h1);
            *(__nv_bfloat162*)(ctxl + (size_t)m * D_ + n) = __nv_bfloat162(
                __float2bfloat16(v0 - __bfloat162float(h0)),
                __float2bfloat16(v1 - __bfloat162float(h1)));
        }
    }
}

// ============================================================================
// host launcher
// ============================================================================
extern "C" void kernel_launch(void* const* d_in, const int* in_sizes, int n_in,
                              void* d_out, int out_size)
{
    const float* src = (const float*)d_in[0];
    const float* Wq  = (const float*)d_in[1];
    const float* bq  = (const float*)d_in[2];
    const float* Wk  = (const float*)d_in[3];
    const float* bk  = (const float*)d_in[4];
    const float* Wv  = (const float*)d_in[5];
    const float* bv  = (const float*)d_in[6];
    const float* Wo  = (const float*)d_in[7];
    const float* bo  = (const float*)d_in[8];
    const float* cw  = (const float*)d_in[9];
    const float* cb  = (const float*)d_in[10];

    float* out      = (float*)d_out;
    float* attn_out = out + OUT_ELEMS;

    float* salp;
    __nv_bfloat16 *Ahi, *Alo, *Whi, *Wlo;
    __nv_bfloat16 *Qh, *Ql, *Kh, *Kl, *Vh, *Vl;
    cudaGetSymbolAddress((void**)&salp, g_sal);
    cudaGetSymbolAddress((void**)&Ahi,  g_Ahi);
    cudaGetSymbolAddress((void**)&Alo,  g_Alo);
    cudaGetSymbolAddress((void**)&Whi,  g_Whi);
    cudaGetSymbolAddress((void**)&Wlo,  g_Wlo);
    cudaGetSymbolAddress((void**)&Qh,   g_Qh);
    cudaGetSymbolAddress((void**)&Ql,   g_Ql);
    cudaGetSymbolAddress((void**)&Kh,   g_Kh);
    cudaGetSymbolAddress((void**)&Kl,   g_Kl);
    cudaGetSymbolAddress((void**)&Vh,   g_Vh);
    cudaGetSymbolAddress((void**)&Vl,   g_Vl);

    cudaFuncSetAttribute(conv_sal_kernel,
        cudaFuncAttributeMaxDynamicSharedMemorySize, CONV_SMEM);
    cudaFuncSetAttribute(attn_kernel,
        cudaFuncAttributeMaxDynamicSharedMemorySize, ATTN_SMEM);
    cudaFuncSetAttribute(mma_gemm_bf16x3,
        cudaFuncAttributeMaxDynamicSharedMemorySize, GEMM_SMEM);

    // saliency conv
    conv_sal_kernel<<<B_ * 128, 256, CONV_SMEM>>>(src, cw, cb, salp);

    // bf16 hi/lo splits: src + all 4 weights
    cvt_split<<<(M_ * D_ / 4 + 255) / 256, 256>>>(src, Ahi, Alo, M_ * D_ / 4);
    dim3 wgrid(D_ * D_ / 4 / 256, 4);
    cvt_split_w<<<wgrid, 256>>>(Wq, Wk, Wv, Wo, Whi, Wlo);

    // Q, K, V projections in ONE launch (grid.z selects weight)
    dim3 qkvgrid(8, 32, 3);
    mma_gemm_bf16x3<<<qkvgrid, 256, GEMM_SMEM>>>(Ahi, Alo, Whi, Wlo,
        bq, bk, bv, nullptr, Qh, Ql, Kh, Kl, Vh, Vl, 1);

    // fused tensor-core attention (writes attn + ctx split into Ahi/Alo)
    dim3 agrid(L_ / 16, B_ * H_);
    attn_kernel<<<agrid, 512, ATTN_SMEM>>>(Qh, Ql, Kh, Kl, Vh, Vl, salp,
                                           Ahi, Alo, attn_out);

    // output projection (reads ctx split from Ahi/Alo, Wo = slice 3) -> d_out
    dim3 ogrid(8, 32, 1);
    mma_gemm_bf16x3<<<ogrid, 256, GEMM_SMEM>>>(Ahi, Alo, Whi, Wlo,
        bo, nullptr, nullptr, out, nullptr, nullptr, nullptr, nullptr,
        nullptr, nullptr, 0);
}

// round 15
// speedup vs baseline: 1.4905x; 1.4905x over previous
#include <cuda_runtime.h>
#include <cuda_bf16.h>
#include <cuda_fp16.h>
#include <cstdint>

#define B_ 2
#define L_ 2048
#define D_ 1024
#define H_ 16
#define DH_ 64
#define M_ (B_*L_)
#define OUT_ELEMS (B_*L_*D_)

// -------- scratch (static device arrays; no cudaMalloc allowed) --------
__device__ float g_sal[B_*H_*L_];
__device__ __nv_bfloat16 g_Ahi[M_*D_];
__device__ __nv_bfloat16 g_Alo[M_*D_];
__device__ __nv_bfloat16 g_Whi[4][D_*D_];
__device__ __nv_bfloat16 g_Wlo[4][D_*D_];
__device__ __half g_Qf[B_*H_*L_*DH_];
__device__ __half g_Kf[B_*H_*L_*DH_];
__device__ __half g_Vf[B_*H_*L_*DH_];

__device__ __forceinline__ uint32_t smem_u32(const void* p) {
    uint32_t a;
    asm("{ .reg .u64 t; cvta.to.shared.u64 t, %1; cvt.u32.u64 %0, t; }"
        : "=r"(a) : "l"(p));
    return a;
}

// -------- cp.async helpers --------
#define CP_ASYNC16(dst, src) \
    asm volatile("cp.async.cg.shared.global [%0], [%1], 16;" \
        :: "r"(dst), "l"(src))
#define CP_COMMIT() asm volatile("cp.async.commit_group;")
#define CP_WAIT1()  asm volatile("cp.async.wait_group 1;")
#define CP_WAIT0()  asm volatile("cp.async.wait_group 0;")

// ---------------- mma/ldmatrix primitives ----------------
__device__ __forceinline__ void ldm_x4(uint32_t* r, uint32_t addr) {
    asm volatile("ldmatrix.sync.aligned.m8n8.x4.shared.b16 {%0,%1,%2,%3}, [%4];"
        : "=r"(r[0]), "=r"(r[1]), "=r"(r[2]), "=r"(r[3]) : "r"(addr));
}
__device__ __forceinline__ void ldm_x2(uint32_t* r, uint32_t addr) {
    asm volatile("ldmatrix.sync.aligned.m8n8.x2.shared.b16 {%0,%1}, [%2];"
        : "=r"(r[0]), "=r"(r[1]) : "r"(addr));
}
__device__ __forceinline__ void ldm_x2_t(uint32_t* r, uint32_t addr) {
    asm volatile("ldmatrix.sync.aligned.m8n8.x2.trans.shared.b16 {%0,%1}, [%2];"
        : "=r"(r[0]), "=r"(r[1]) : "r"(addr));
}
__device__ __forceinline__ void mma16816(float* c, const uint32_t* a, const uint32_t* b) {
    asm volatile(
        "mma.sync.aligned.m16n8k16.row.col.f32.bf16.bf16.f32 "
        "{%0,%1,%2,%3}, {%4,%5,%6,%7}, {%8,%9}, {%0,%1,%2,%3};"
        : "+f"(c[0]), "+f"(c[1]), "+f"(c[2]), "+f"(c[3])
        : "r"(a[0]), "r"(a[1]), "r"(a[2]), "r"(a[3]), "r"(b[0]), "r"(b[1]));
}
__device__ __forceinline__ void mma16816h(float* c, const uint32_t* a, const uint32_t* b) {
    asm volatile(
        "mma.sync.aligned.m16n8k16.row.col.f32.f16.f16.f32 "
        "{%0,%1,%2,%3}, {%4,%5,%6,%7}, {%8,%9}, {%0,%1,%2,%3};"
        : "+f"(c[0]), "+f"(c[1]), "+f"(c[2]), "+f"(c[3])
        : "r"(a[0]), "r"(a[1]), "r"(a[2]), "r"(a[3]), "r"(b[0]), "r"(b[1]));
}

// ============================================================================
// fp32 -> bf16 hi/lo split (vectorized)
// ============================================================================
__global__ void __launch_bounds__(256) cvt_split(
    const float* __restrict__ x, __nv_bfloat16* __restrict__ hi,
    __nv_bfloat16* __restrict__ lo, int n4)
{
    int i = blockIdx.x * blockDim.x + threadIdx.x;
    if (i >= n4) return;
    float4 v = ((const float4*)x)[i];
    __nv_bfloat16 h0 = __float2bfloat16(v.x);
    __nv_bfloat16 h1 = __float2bfloat16(v.y);
    __nv_bfloat16 h2 = __float2bfloat16(v.z);
    __nv_bfloat16 h3 = __float2bfloat16(v.w);
    __nv_bfloat162* hp = (__nv_bfloat162*)hi;
    __nv_bfloat162* lp = (__nv_bfloat162*)lo;
    hp[2 * i]     = __nv_bfloat162(h0, h1);
    hp[2 * i + 1] = __nv_bfloat162(h2, h3);
    lp[2 * i]     = __nv_bfloat162(__float2bfloat16(v.x - __bfloat162float(h0)),
                                   __float2bfloat16(v.y - __bfloat162float(h1)));
    lp[2 * i + 1] = __nv_bfloat162(__float2bfloat16(v.z - __bfloat162float(h2)),
                                   __float2bfloat16(v.w - __bfloat162float(h3)));
}

// 4 weights in one launch: grid.y selects the matrix
__global__ void __launch_bounds__(256) cvt_split_w(
    const float* __restrict__ w0, const float* __restrict__ w1,
    const float* __restrict__ w2, const float* __restrict__ w3,
    __nv_bfloat16* __restrict__ hi, __nv_bfloat16* __restrict__ lo)
{
    const int wsel = blockIdx.y;
    const float* x = (wsel == 0) ? w0 : (wsel == 1) ? w1 : (wsel == 2) ? w2 : w3;
    int i = blockIdx.x * blockDim.x + threadIdx.x;
    float4 v = ((const float4*)x)[i];
    size_t off = (size_t)wsel * (D_ * D_ / 2) + 2 * (size_t)i;
    __nv_bfloat16 h0 = __float2bfloat16(v.x);
    __nv_bfloat16 h1 = __float2bfloat16(v.y);
    __nv_bfloat16 h2 = __float2bfloat16(v.z);
    __nv_bfloat16 h3 = __float2bfloat16(v.w);
    ((__nv_bfloat162*)hi)[off]     = __nv_bfloat162(h0, h1);
    ((__nv_bfloat162*)hi)[off + 1] = __nv_bfloat162(h2, h3);
    ((__nv_bfloat162*)lo)[off]     = __nv_bfloat162(
        __float2bfloat16(v.x - __bfloat162float(h0)),
        __float2bfloat16(v.y - __bfloat162float(h1)));
    ((__nv_bfloat162*)lo)[off + 1] = __nv_bfloat162(
        __float2bfloat16(v.z - __bfloat162float(h2)),
        __float2bfloat16(v.w - __bfloat162float(h3)));
}

// ============================================================================
// mma.sync bf16x3 GEMM, cp.async double-buffered; 2 CTAs/SM. (R12 ordering)
// qkv=1: grid.z selects W slice + bias; headed fp16 dest (Qf/Kf/Vf).
// qkv=0: Wo -> fp32 C.
// ============================================================================
#define TSTRIDE 40
#define GSTAGE 40960
#define GEMM_SMEM (2 * GSTAGE)

__global__ void __launch_bounds__(256, 2) mma_gemm_bf16x3(
    const __nv_bfloat16* __restrict__ Ah, const __nv_bfloat16* __restrict__ Al,
    const __nv_bfloat16* __restrict__ Wh0, const __nv_bfloat16* __restrict__ Wl0,
    const float* __restrict__ b0, const float* __restrict__ b1,
    const float* __restrict__ b2,
    float* __restrict__ C,
    __half* __restrict__ Qf, __half* __restrict__ Kf, __half* __restrict__ Vf,
    int qkv)
{
    extern __shared__ __align__(128) char smg[];
    const uint32_t smb = smem_u32(smg);

    const int tid = threadIdx.x;
    const int wid = tid >> 5;
    const int lane = tid & 31;
    const int wm = (wid & 1) * 64;
    const int wn = (wid >> 1) * 32;
    const int m0 = blockIdx.y * 128;
    const int n0 = blockIdx.x * 128;
    const int z = qkv ? blockIdx.z : 3;

    const __nv_bfloat16* Bh = Wh0 + (size_t)z * D_ * D_;
    const __nv_bfloat16* Bl = Wl0 + (size_t)z * D_ * D_;
    const float* bias = qkv ? (z == 0 ? b0 : (z == 1 ? b1 : b2)) : b0;
    __half* Cf = qkv ? (z == 0 ? Qf : (z == 1 ? Kf : Vf)) : nullptr;

    float c[4][4][4];
#pragma unroll
    for (int i = 0; i < 4; ++i)
#pragma unroll
        for (int j = 0; j < 4; ++j)
#pragma unroll
            for (int r = 0; r < 4; ++r) c[i][j][r] = 0.f;

    auto issue = [&](int i, int st) {
        const int k0 = i * 32;
        const uint32_t sb = smb + st * GSTAGE;
#pragma unroll
        for (int t = 0; t < 2; ++t) {
            int idx = t * 256 + tid;
            int row = idx >> 2, sub = idx & 3;
            uint32_t off = (uint32_t)(row * TSTRIDE + sub * 8) * 2;
            size_t ga = (size_t)(m0 + row) * D_ + k0 + sub * 8;
            size_t gb = (size_t)(n0 + row) * D_ + k0 + sub * 8;
            CP_ASYNC16(sb + off,         Ah + ga);
            CP_ASYNC16(sb + 10240 + off, Al + ga);
            CP_ASYNC16(sb + 20480 + off, Bh + gb);
            CP_ASYNC16(sb + 30720 + off, Bl + gb);
        }
    };

    const int arow = lane & 15, acol = (lane >> 4) << 3;
    const int brow = lane & 7,  bcol = ((lane >> 3) & 1) << 3;

    issue(0, 0); CP_COMMIT();
    issue(1, 1); CP_COMMIT();

    for (int i = 0; i < 32; ++i) {
        if (i < 31) CP_WAIT1(); else CP_WAIT0();
        __syncthreads();
        const uint32_t aB = smb + (i & 1) * GSTAGE;

#pragma unroll
        for (int ks = 0; ks < 2; ++ks) {
            const int kk = ks * 16;
            uint32_t ah[4][4], al[4][4];
#pragma unroll
            for (int mt = 0; mt < 4; ++mt) {
                uint32_t off = (uint32_t)((wm + mt * 16 + arow) * TSTRIDE + kk + acol) * 2;
                ldm_x4(ah[mt], aB + off);
                ldm_x4(al[mt], aB + 10240 + off);
            }
#pragma unroll
            for (int nt = 0; nt < 4; ++nt) {
                uint32_t boff = (uint32_t)((wn + nt * 8 + brow) * TSTRIDE + kk + bcol) * 2;
                uint32_t bh[2], bl[2];
                ldm_x2(bh, aB + 20480 + boff);
                ldm_x2(bl, aB + 30720 + boff);
#pragma unroll
                for (int mt = 0; mt < 4; ++mt) {
                    mma16816(c[mt][nt], ah[mt], bh);
                    mma16816(c[mt][nt], ah[mt], bl);
                    mma16816(c[mt][nt], al[mt], bh);
                }
            }
        }
        __syncthreads();
        if (i + 2 < 32) { issue(i + 2, i & 1); CP_COMMIT(); }
    }

    const int rl = lane >> 2;
    const int cl = (lane & 3) * 2;
#pragma unroll
    for (int mt = 0; mt < 4; ++mt) {
#pragma unroll
        for (int half = 0; half < 2; ++half) {
            int m = m0 + wm + mt * 16 + rl + half * 8;
            int b = m >> 11, l = m & 2047;
#pragma unroll
            for (int nt = 0; nt < 4; ++nt) {
                int n = n0 + wn + nt * 8 + cl;
                float v0 = c[mt][nt][half * 2 + 0] + bias[n];
                float v1 = c[mt][nt][half * 2 + 1] + bias[n + 1];
                if (!qkv) {
                    *(float2*)(C + (size_t)m * D_ + n) = make_float2(v0, v1);
                } else {
                    int h = n >> 6, dh = n & 63;
                    size_t off = (size_t)(((b << 4) + h) * 2048 + l) * 64 + dh;
                    *(__half2*)(Cf + off) =
                        __halves2half2(__float2half(v0), __float2half(v1));
                }
            }
        }
    }
}

// ============================================================================
// Saliency Conv1d(D->H, k=3, pad=1): sal[b,h,l]
// ============================================================================
#define CONV_SMEM (18 * 1028 * 4)
__global__ void __launch_bounds__(256) conv_sal_kernel(
    const float* __restrict__ src, const float* __restrict__ cw,
    const float* __restrict__ cb, float* __restrict__ sal)
{
    extern __shared__ float ss[];
    const int bid = blockIdx.x;
    const int b = bid >> 7, lt = bid & 127;
    const int l0 = lt * 16;
    const int tid = threadIdx.x;

#pragma unroll
    for (int it = 0; it < 18; ++it) {
        int idx = it * 256 + tid;
        int row = idx >> 8;
        int c4 = idx & 255;
        int gl = l0 + row - 1;
        float4 v = make_float4(0.f, 0.f, 0.f, 0.f);
        if (gl >= 0 && gl < L_)
            v = *(const float4*)(src + ((size_t)b * L_ + gl) * D_ + c4 * 4);
        *(float4*)(ss + row * 1028 + c4 * 4) = v;
    }
    __syncthreads();

    const int h = tid >> 4, li = tid & 15;
    const float* wp = cw + (size_t)h * D_ * 3;
    float acc = 0.f;
#pragma unroll 4
    for (int d = 0; d < D_; ++d) {
        float w0 = wp[d * 3 + 0], w1 = wp[d * 3 + 1], w2 = wp[d * 3 + 2];
        acc = fmaf(ss[(li + 0) * 1028 + d], w0, acc);
        acc = fmaf(ss[(li + 1) * 1028 + d], w1, acc);
        acc = fmaf(ss[(li + 2) * 1028 + d], w2, acc);
    }
    sal[(size_t)(b * H_ + h) * L_ + l0 + li] = acc + cb[h];
}

// ============================================================================
// Fused PURE-FP16 tensor-core attention, 512 threads, small smem (2 CTAs/SM):
//  Phase1: per-warp fp16 K streaming (barrier-free); S=exp(QK/8+sal+ln32)
//          stored as SINGLE fp16 P (scaled x32; scale cancels in normalize).
//  Phase2: CTA-shared fp16 V staging; 1-term PV; attn = P*inv; ctx = cc*inv.
// SMEM (bytes):
//  P  16x2056 fp16 @ 0        65,792
//  K slices / V   @ 65,792    36,864  (ph1: 16w x 2st x 1152B; ph2: 2x18,432;
//                                      reused as 8KB ctx-reduction at end)
//  Q  16x72 fp16  @ 102,656   2,304
//  sum 16x16 f32  @ 104,960   1,024
//  inv 16 f32     @ 105,984   64
// ============================================================================
#define PH_PITCH 2056
#define KV_OFF  65792
#define V_STG   18432
#define SL_WARP 2304
#define SL_STG  1152
#define RED_OFF 65792
#define Q_OFF   102656
#define SUM_OFF 104960
#define INV_OFF 105984
#define ATTN_SMEM 106048
#define LN32 3.4657359027997265f

__global__ void __launch_bounds__(512) attn_kernel(
    const __half* __restrict__ Qf, const __half* __restrict__ Kf,
    const __half* __restrict__ Vf,
    const float* __restrict__ sal,
    __nv_bfloat16* __restrict__ ctxh, __nv_bfloat16* __restrict__ ctxl,
    float* __restrict__ attn)
{
    extern __shared__ __align__(128) char smem[];
    __half* sP  = (__half*)smem;
    float* sSum = (float*)(smem + SUM_OFF);
    float* sInv = (float*)(smem + INV_OFF);
    const uint32_t smb = smem_u32(smem);
    const uint32_t pB = smb;

    const int tid = threadIdx.x;
    const int wid = tid >> 5;
    const int lane = tid & 31;
    const int q0 = blockIdx.x * 16;
    const int bh = blockIdx.y;
    const size_t base = (size_t)bh * (L_ * DH_);
    const float* salRow = sal + (size_t)bh * L_;
    const uint32_t wsl = smb + KV_OFF + wid * SL_WARP;

    // stage Q tile (16 rows x 64 fp16, pitch 72)
    if (tid < 128) {
        int r = tid >> 3, s = tid & 7;
        const uint4* gq = (const uint4*)(Qf + base + (size_t)q0 * DH_);
        *(uint4*)((__half*)(smem + Q_OFF) + r * 72 + s * 8) = gq[tid];
    }
    __syncthreads();

    // preload Q fragments (m16 x k64)
    const int arow = lane & 15, acol = (lane >> 4) << 3;
    const int brow = lane & 7;
    const uint32_t bcol16 = ((lane >> 3) & 1) << 4;
    uint32_t fQ[4][4];
    {
        const uint32_t qB = smb + Q_OFF;
#pragma unroll
        for (int ks = 0; ks < 4; ++ks)
            ldm_x4(fQ[ks], qB + (uint32_t)(arow * 72 + ks * 16 + acol) * 2);
    }

    // per-warp K slice: 8 rows x 64 fp16 (pitch 144B)
    auto issueK = [&](int kt, int st) {
        const uint32_t sb = wsl + st * SL_STG;
        const size_t gk = base + (size_t)(kt * 128 + wid * 8) * DH_;
#pragma unroll
        for (int j = 0; j < 2; ++j) {
            int id = lane + 32 * j;
            int row = id >> 3, seg = id & 7;
            CP_ASYNC16(sb + (uint32_t)(row * 144 + seg * 16),
                       Kf + gk + (size_t)row * DH_ + seg * 8);
        }
    };
    // CTA-shared V stage (128 rows x 64 fp16, pitch 144B)
    auto issueV = [&](int t128, int st) {
        const uint32_t sb = smb + KV_OFF + st * V_STG;
        const __half* pv = Vf + base + (size_t)t128 * 128 * DH_;
#pragma unroll
        for (int t = 0; t < 2; ++t) {
            int idx = t * 512 + tid;
            int r = idx >> 3, s = idx & 7;
            CP_ASYNC16(sb + (uint32_t)(r * 144 + s * 16),
                       pv + (size_t)r * DH_ + s * 8);
        }
    };

    // ---- Phase 1: per-warp streaming, fp16, barrier-free ----
    issueK(0, 0); CP_COMMIT();
    issueK(1, 1); CP_COMMIT();

    float sum_lo = 0.f, sum_hi = 0.f;
    const int row4 = lane >> 2;
    const int colw = wid * 8 + (lane & 3) * 2;
    float2 salc = *(const float2*)(salRow + colw);
    for (int kt = 0; kt < 16; ++kt) {
        if (kt < 15) CP_WAIT1(); else CP_WAIT0();
        __syncwarp();
        const uint32_t kb = wsl + (kt & 1) * SL_STG;

        float c[4] = {0.f, 0.f, 0.f, 0.f};
        uint32_t bo = kb + (uint32_t)(brow * 144) + bcol16;
#pragma unroll
        for (int ks = 0; ks < 4; ++ks) {
            uint32_t kf[2];
            ldm_x2(kf, bo + ks * 32);
            mma16816h(c, fQ[ks], kf);
        }
        if (kt + 2 < 16) { issueK(kt + 2, kt & 1); CP_COMMIT(); }

        float2 saln;
        if (kt < 15) saln = *(const float2*)(salRow + (kt + 1) * 128 + colw);

        float e0 = __expf(fmaf(c[0], 0.125f, salc.x) + LN32);
        float e1 = __expf(fmaf(c[1], 0.125f, salc.y) + LN32);
        float e2 = __expf(fmaf(c[2], 0.125f, salc.x) + LN32);
        float e3 = __expf(fmaf(c[3], 0.125f, salc.y) + LN32);
        int col = kt * 128 + colw;
        *(__half2*)(sP + row4 * PH_PITCH + col) =
            __halves2half2(__float2half(e0), __float2half(e1));
        *(__half2*)(sP + (row4 + 8) * PH_PITCH + col) =
            __halves2half2(__float2half(e2), __float2half(e3));
        sum_lo += e0 + e1;
        sum_hi += e2 + e3;
        salc = saln;
    }

    // ---- row-sum reduction (phase boundary) ----
    sum_lo += __shfl_xor_sync(0xffffffffu, sum_lo, 1);
    sum_lo += __shfl_xor_sync(0xffffffffu, sum_lo, 2);
    sum_hi += __shfl_xor_sync(0xffffffffu, sum_hi, 1);
    sum_hi += __shfl_xor_sync(0xffffffffu, sum_hi, 2);
    if ((lane & 3) == 0) {
        sSum[row4 * 16 + wid] = sum_lo;
        sSum[(row4 + 8) * 16 + wid] = sum_hi;
    }
    __syncthreads();   // K-slice reads done; sums published

    issueV(0, 0); CP_COMMIT();
    issueV(1, 1); CP_COMMIT();

    if (tid < 16) {
        float s = 0.f;
#pragma unroll
        for (int j = 0; j < 16; ++j) s += sSum[tid * 16 + j];
        sInv[tid] = 1.f / s;
    }
    __syncthreads();

    // ---- Phase 2: attn write + 1-term fp16 PV (k split across warp pairs) ----
    const int n8p = wid & 7;
    const int kh = wid >> 3;
    float cc[4] = {0.f, 0.f, 0.f, 0.f};

    for (int lt = 0; lt < 16; ++lt) {
        if (lt < 15) CP_WAIT1(); else CP_WAIT0();
        __syncthreads();

        // attn write: one warp per row, attn = P * inv (scale cancels)
        {
            int row = wid;
            float inv = sInv[row];
            int c0 = lt * 128 + lane * 4;
            __half2 a0 = *(const __half2*)(sP + row * PH_PITCH + c0);
            __half2 a1 = *(const __half2*)(sP + row * PH_PITCH + c0 + 2);
            float4 v;
            v.x = __half2float(a0.x) * inv;
            v.y = __half2float(a0.y) * inv;
            v.z = __half2float(a1.x) * inv;
            v.w = __half2float(a1.y) * inv;
            *(float4*)(attn + ((size_t)bh * L_ + q0 + row) * L_ + c0) = v;
        }

        const uint32_t vb = smb + KV_OFF + (lt & 1) * V_STG;
#pragma unroll
        for (int ksl = 0; ksl < 4; ++ksl) {
            int ks = kh * 4 + ksl;
            int kp = lt * 128 + ks * 16;
            uint32_t fA[4];
            ldm_x4(fA, pB + (uint32_t)(arow * PH_PITCH + kp + acol) * 2);
            uint32_t fV[2];
            ldm_x2_t(fV, vb + (uint32_t)((ks * 16 + (lane & 15)) * 144 + n8p * 16));
            mma16816h(cc, fA, fV);
        }
        __syncthreads();
        if (lt + 2 < 16) { issueV(lt + 2, lt & 1); CP_COMMIT(); }
    }

    // ---- reduce ctx partials across warp pairs, write split bf16 ----
    float* red = (float*)(smem + RED_OFF);
    *(float4*)(red + wid * 128 + lane * 4) = make_float4(cc[0], cc[1], cc[2], cc[3]);
    __syncthreads();
    if (wid < 8) {
        float4 p = *(const float4*)(red + wid * 128 + lane * 4);
        float4 q = *(const float4*)(red + (wid + 8) * 128 + lane * 4);
        float v[4] = {p.x + q.x, p.y + q.y, p.z + q.z, p.w + q.w};
        int row = lane >> 2;
        int colp = (lane & 3) * 2;
        int b = bh >> 4, h = bh & 15;
        int n = h * 64 + wid * 8 + colp;
#pragma unroll
        for (int half = 0; half < 2; ++half) {
            int r = row + half * 8;
            float inv = sInv[r];
            int m = b * 2048 + q0 + r;
            float v0 = v[half * 2 + 0] * inv, v1 = v[half * 2 + 1] * inv;
            __nv_bfloat16 h0 = __float2bfloat16(v0);
            __nv_bfloat16 h1 = __float2bfloat16(v1);
            *(__nv_bfloat162*)(ctxh + (size_t)m * D_ + n) = __nv_bfloat162(h0, h1);
            *(__nv_bfloat162*)(ctxl + (size_t)m * D_ + n) = __nv_bfloat162(
                __float2bfloat16(v0 - __bfloat162float(h0)),
                __float2bfloat16(v1 - __bfloat162float(h1)));
        }
    }
}

// ============================================================================
// host launcher
// ============================================================================
extern "C" void kernel_launch(void* const* d_in, const int* in_sizes, int n_in,
                              void* d_out, int out_size)
{
    const float* src = (const float*)d_in[0];
    const float* Wq  = (const float*)d_in[1];
    const float* bq  = (const float*)d_in[2];
    const float* Wk  = (const float*)d_in[3];
    const float* bk  = (const float*)d_in[4];
    const float* Wv  = (const float*)d_in[5];
    const float* bv  = (const float*)d_in[6];
    const float* Wo  = (const float*)d_in[7];
    const float* bo  = (const float*)d_in[8];
    const float* cw  = (const float*)d_in[9];
    const float* cb  = (const float*)d_in[10];

    float* out      = (float*)d_out;
    float* attn_out = out + OUT_ELEMS;

    float* salp;
    __nv_bfloat16 *Ahi, *Alo, *Whi, *Wlo;
    __half *Qf, *Kf, *Vf;
    cudaGetSymbolAddress((void**)&salp, g_sal);
    cudaGetSymbolAddress((void**)&Ahi,  g_Ahi);
    cudaGetSymbolAddress((void**)&Alo,  g_Alo);
    cudaGetSymbolAddress((void**)&Whi,  g_Whi);
    cudaGetSymbolAddress((void**)&Wlo,  g_Wlo);
    cudaGetSymbolAddress((void**)&Qf,   g_Qf);
    cudaGetSymbolAddress((void**)&Kf,   g_Kf);
    cudaGetSymbolAddress((void**)&Vf,   g_Vf);

    cudaFuncSetAttribute(conv_sal_kernel,
        cudaFuncAttributeMaxDynamicSharedMemorySize, CONV_SMEM);
    cudaFuncSetAttribute(attn_kernel,
        cudaFuncAttributeMaxDynamicSharedMemorySize, ATTN_SMEM);
    cudaFuncSetAttribute(mma_gemm_bf16x3,
        cudaFuncAttributeMaxDynamicSharedMemorySize, GEMM_SMEM);

    // saliency conv
    conv_sal_kernel<<<B_ * 128, 256, CONV_SMEM>>>(src, cw, cb, salp);

    // bf16 hi/lo splits: src + all 4 weights
    cvt_split<<<(M_ * D_ / 4 + 255) / 256, 256>>>(src, Ahi, Alo, M_ * D_ / 4);
    dim3 wgrid(D_ * D_ / 4 / 256, 4);
    cvt_split_w<<<wgrid, 256>>>(Wq, Wk, Wv, Wo, Whi, Wlo);

    // Q, K, V projections in ONE launch -> fp16 headed layout
    dim3 qkvgrid(8, 32, 3);
    mma_gemm_bf16x3<<<qkvgrid, 256, GEMM_SMEM>>>(Ahi, Alo, Whi, Wlo,
        bq, bk, bv, nullptr, Qf, Kf, Vf, 1);

    // fused fp16 tensor-core attention (writes attn + ctx split into Ahi/Alo)
    dim3 agrid(L_ / 16, B_ * H_);
    attn_kernel<<<agrid, 512, ATTN_SMEM>>>(Qf, Kf, Vf, salp,
                                           Ahi, Alo, attn_out);

    // output projection (reads ctx split from Ahi/Alo, Wo = slice 3) -> d_out
    dim3 ogrid(8, 32, 1);
    mma_gemm_bf16x3<<<ogrid, 256, GEMM_SMEM>>>(Ahi, Alo, Whi, Wlo,
        bo, nullptr, nullptr, out, nullptr, nullptr, nullptr, 0);
}

// round 17
// speedup vs baseline: 1.6312x; 1.0944x over previous
#include <cuda_runtime.h>
#include <cuda_bf16.h>
#include <cuda_fp16.h>
#include <cstdint>

#define B_ 2
#define L_ 2048
#define D_ 1024
#define H_ 16
#define DH_ 64
#define M_ (B_*L_)
#define OUT_ELEMS (B_*L_*D_)

// -------- scratch (static device arrays; no cudaMalloc allowed) --------
__device__ float g_sal[B_*H_*L_];
__device__ __half g_Af[M_*D_];                 // src fp16 (QKV A operand)
__device__ __half g_Whf[3][D_*D_];             // Wq/Wk/Wv fp16 hi
__device__ __half g_Wlf[3][D_*D_];             // Wq/Wk/Wv fp16 lo
__device__ __nv_bfloat16 g_Ahi[M_*D_];         // ctx bf16 hi (attn -> Wo)
__device__ __nv_bfloat16 g_Alo[M_*D_];
__device__ __nv_bfloat16 g_Whi[4][D_*D_];      // slice 3 = Wo bf16 hi
__device__ __nv_bfloat16 g_Wlo[4][D_*D_];
__device__ __half g_Qf[B_*H_*L_*DH_];
__device__ __half g_Kf[B_*H_*L_*DH_];
__device__ __half g_Vf[B_*H_*L_*DH_];

__device__ __forceinline__ uint32_t smem_u32(const void* p) {
    uint32_t a;
    asm("{ .reg .u64 t; cvta.to.shared.u64 t, %1; cvt.u32.u64 %0, t; }"
        : "=r"(a) : "l"(p));
    return a;
}

// -------- cp.async helpers --------
#define CP_ASYNC16(dst, src) \
    asm volatile("cp.async.cg.shared.global [%0], [%1], 16;" \
        :: "r"(dst), "l"(src))
#define CP_COMMIT() asm volatile("cp.async.commit_group;")
#define CP_WAIT1()  asm volatile("cp.async.wait_group 1;")
#define CP_WAIT0()  asm volatile("cp.async.wait_group 0;")

// ---------------- mma/ldmatrix primitives ----------------
__device__ __forceinline__ void ldm_x4(uint32_t* r, uint32_t addr) {
    asm volatile("ldmatrix.sync.aligned.m8n8.x4.shared.b16 {%0,%1,%2,%3}, [%4];"
        : "=r"(r[0]), "=r"(r[1]), "=r"(r[2]), "=r"(r[3]) : "r"(addr));
}
__device__ __forceinline__ void ldm_x2(uint32_t* r, uint32_t addr) {
    asm volatile("ldmatrix.sync.aligned.m8n8.x2.shared.b16 {%0,%1}, [%2];"
        : "=r"(r[0]), "=r"(r[1]) : "r"(addr));
}
__device__ __forceinline__ void ldm_x2_t(uint32_t* r, uint32_t addr) {
    asm volatile("ldmatrix.sync.aligned.m8n8.x2.trans.shared.b16 {%0,%1}, [%2];"
        : "=r"(r[0]), "=r"(r[1]) : "r"(addr));
}
__device__ __forceinline__ void mma16816(float* c, const uint32_t* a, const uint32_t* b) {
    asm volatile(
        "mma.sync.aligned.m16n8k16.row.col.f32.bf16.bf16.f32 "
        "{%0,%1,%2,%3}, {%4,%5,%6,%7}, {%8,%9}, {%0,%1,%2,%3};"
        : "+f"(c[0]), "+f"(c[1]), "+f"(c[2]), "+f"(c[3])
        : "r"(a[0]), "r"(a[1]), "r"(a[2]), "r"(a[3]), "r"(b[0]), "r"(b[1]));
}
__device__ __forceinline__ void mma16816h(float* c, const uint32_t* a, const uint32_t* b) {
    asm volatile(
        "mma.sync.aligned.m16n8k16.row.col.f32.f16.f16.f32 "
        "{%0,%1,%2,%3}, {%4,%5,%6,%7}, {%8,%9}, {%0,%1,%2,%3};"
        : "+f"(c[0]), "+f"(c[1]), "+f"(c[2]), "+f"(c[3])
        : "r"(a[0]), "r"(a[1]), "r"(a[2]), "r"(a[3]), "r"(b[0]), "r"(b[1]));
}

// ============================================================================
// fp32 -> fp16 (src, for QKV A operand)
// ============================================================================
__global__ void __launch_bounds__(256) cvt_src_f16(
    const float* __restrict__ x, __half* __restrict__ y, int n4)
{
    int i = blockIdx.x * blockDim.x + threadIdx.x;
    if (i >= n4) return;
    float4 v = ((const float4*)x)[i];
    __half2* yp = (__half2*)y;
    yp[2 * i]     = __halves2half2(__float2half(v.x), __float2half(v.y));
    yp[2 * i + 1] = __halves2half2(__float2half(v.z), __float2half(v.w));
}

// Weights: z<3 -> fp16 hi/lo (Wq/Wk/Wv); z==3 -> bf16 hi/lo (Wo, slice 3)
__global__ void __launch_bounds__(256) cvt_w_mixed(
    const float* __restrict__ w0, const float* __restrict__ w1,
    const float* __restrict__ w2, const float* __restrict__ w3,
    __half* __restrict__ hf, __half* __restrict__ lf,
    __nv_bfloat16* __restrict__ hi, __nv_bfloat16* __restrict__ lo)
{
    const int wsel = blockIdx.y;
    const float* x = (wsel == 0) ? w0 : (wsel == 1) ? w1 : (wsel == 2) ? w2 : w3;
    int i = blockIdx.x * blockDim.x + threadIdx.x;
    float4 v = ((const float4*)x)[i];
    if (wsel < 3) {
        size_t off = (size_t)wsel * (D_ * D_ / 2) + 2 * (size_t)i;
        __half h0 = __float2half(v.x), h1 = __float2half(v.y);
        __half h2 = __float2half(v.z), h3 = __float2half(v.w);
        ((__half2*)hf)[off]     = __halves2half2(h0, h1);
        ((__half2*)hf)[off + 1] = __halves2half2(h2, h3);
        ((__half2*)lf)[off]     = __halves2half2(
            __float2half(v.x - __half2float(h0)),
            __float2half(v.y - __half2float(h1)));
        ((__half2*)lf)[off + 1] = __halves2half2(
            __float2half(v.z - __half2float(h2)),
            __float2half(v.w - __half2float(h3)));
    } else {
        size_t off = (size_t)3 * (D_ * D_ / 2) + 2 * (size_t)i;
        __nv_bfloat16 h0 = __float2bfloat16(v.x);
        __nv_bfloat16 h1 = __float2bfloat16(v.y);
        __nv_bfloat16 h2 = __float2bfloat16(v.z);
        __nv_bfloat16 h3 = __float2bfloat16(v.w);
        ((__nv_bfloat162*)hi)[off]     = __nv_bfloat162(h0, h1);
        ((__nv_bfloat162*)hi)[off + 1] = __nv_bfloat162(h2, h3);
        ((__nv_bfloat162*)lo)[off]     = __nv_bfloat162(
            __float2bfloat16(v.x - __bfloat162float(h0)),
            __float2bfloat16(v.y - __bfloat162float(h1)));
        ((__nv_bfloat162*)lo)[off + 1] = __nv_bfloat162(
            __float2bfloat16(v.z - __bfloat162float(h2)),
            __float2bfloat16(v.w - __bfloat162float(h3)));
    }
}

// ============================================================================
// QKV GEMM: fp16x2 (A single fp16, W split fp16 hi/lo; C = A*Bh + A*Bl)
// cp.async double-buffered, 2 CTAs/SM. grid.z selects W slice + bias + dest.
// ============================================================================
#define TSTRIDE 40
#define GSTAGE2 30720                  // 3 tiles x 128*40*2
#define GEMM2_SMEM (2 * GSTAGE2)

__global__ void __launch_bounds__(256, 2) mma_gemm_f16x2(
    const __half* __restrict__ A,
    const __half* __restrict__ Wh0, const __half* __restrict__ Wl0,
    const float* __restrict__ b0, const float* __restrict__ b1,
    const float* __restrict__ b2,
    __half* __restrict__ Qf, __half* __restrict__ Kf, __half* __restrict__ Vf)
{
    extern __shared__ __align__(128) char smg[];
    const uint32_t smb = smem_u32(smg);

    const int tid = threadIdx.x;
    const int wid = tid >> 5;
    const int lane = tid & 31;
    const int wm = (wid & 1) * 64;
    const int wn = (wid >> 1) * 32;
    const int m0 = blockIdx.y * 128;
    const int n0 = blockIdx.x * 128;
    const int z = blockIdx.z;

    const __half* Bh = Wh0 + (size_t)z * D_ * D_;
    const __half* Bl = Wl0 + (size_t)z * D_ * D_;
    const float* bias = z == 0 ? b0 : (z == 1 ? b1 : b2);
    __half* Cf = z == 0 ? Qf : (z == 1 ? Kf : Vf);

    float c[4][4][4];
#pragma unroll
    for (int i = 0; i < 4; ++i)
#pragma unroll
        for (int j = 0; j < 4; ++j)
#pragma unroll
            for (int r = 0; r < 4; ++r) c[i][j][r] = 0.f;

    auto issue = [&](int i, int st) {
        const int k0 = i * 32;
        const uint32_t sb = smb + st * GSTAGE2;
#pragma unroll
        for (int t = 0; t < 2; ++t) {
            int idx = t * 256 + tid;
            int row = idx >> 2, sub = idx & 3;
            uint32_t off = (uint32_t)(row * TSTRIDE + sub * 8) * 2;
            size_t ga = (size_t)(m0 + row) * D_ + k0 + sub * 8;
            size_t gb = (size_t)(n0 + row) * D_ + k0 + sub * 8;
            CP_ASYNC16(sb + off,         A + ga);
            CP_ASYNC16(sb + 10240 + off, Bh + gb);
            CP_ASYNC16(sb + 20480 + off, Bl + gb);
        }
    };

    const int arow = lane & 15, acol = (lane >> 4) << 3;
    const int brow = lane & 7,  bcol = ((lane >> 3) & 1) << 3;

    issue(0, 0); CP_COMMIT();
    issue(1, 1); CP_COMMIT();

    for (int i = 0; i < 32; ++i) {
        if (i < 31) CP_WAIT1(); else CP_WAIT0();
        __syncthreads();
        const uint32_t aB = smb + (i & 1) * GSTAGE2;

#pragma unroll
        for (int ks = 0; ks < 2; ++ks) {
            const int kk = ks * 16;
            uint32_t a[4][4];
#pragma unroll
            for (int mt = 0; mt < 4; ++mt)
                ldm_x4(a[mt], aB + (uint32_t)((wm + mt * 16 + arow) * TSTRIDE + kk + acol) * 2);
#pragma unroll
            for (int nt = 0; nt < 4; ++nt) {
                uint32_t boff = (uint32_t)((wn + nt * 8 + brow) * TSTRIDE + kk + bcol) * 2;
                uint32_t bh[2], bl[2];
                ldm_x2(bh, aB + 10240 + boff);
                ldm_x2(bl, aB + 20480 + boff);
#pragma unroll
                for (int mt = 0; mt < 4; ++mt) mma16816h(c[mt][nt], a[mt], bh);
#pragma unroll
                for (int mt = 0; mt < 4; ++mt) mma16816h(c[mt][nt], a[mt], bl);
            }
        }
        __syncthreads();
        if (i + 2 < 32) { issue(i + 2, i & 1); CP_COMMIT(); }
    }

    const int rl = lane >> 2;
    const int cl = (lane & 3) * 2;
#pragma unroll
    for (int mt = 0; mt < 4; ++mt) {
#pragma unroll
        for (int half = 0; half < 2; ++half) {
            int m = m0 + wm + mt * 16 + rl + half * 8;
            int b = m >> 11, l = m & 2047;
#pragma unroll
            for (int nt = 0; nt < 4; ++nt) {
                int n = n0 + wn + nt * 8 + cl;
                float v0 = c[mt][nt][half * 2 + 0] + bias[n];
                float v1 = c[mt][nt][half * 2 + 1] + bias[n + 1];
                int h = n >> 6, dh = n & 63;
                size_t off = (size_t)(((b << 4) + h) * 2048 + l) * 64 + dh;
                *(__half2*)(Cf + off) =
                    __halves2half2(__float2half(v0), __float2half(v1));
            }
        }
    }
}

// ============================================================================
// Wo GEMM: bf16x3 (unchanged R12 structure), ctx split -> fp32 out
// ============================================================================
#define GSTAGE 40960
#define GEMM_SMEM (2 * GSTAGE)

__global__ void __launch_bounds__(256, 2) mma_gemm_bf16x3(
    const __nv_bfloat16* __restrict__ Ah, const __nv_bfloat16* __restrict__ Al,
    const __nv_bfloat16* __restrict__ Bh, const __nv_bfloat16* __restrict__ Bl,
    const float* __restrict__ bias, float* __restrict__ C)
{
    extern __shared__ __align__(128) char smg[];
    const uint32_t smb = smem_u32(smg);

    const int tid = threadIdx.x;
    const int wid = tid >> 5;
    const int lane = tid & 31;
    const int wm = (wid & 1) * 64;
    const int wn = (wid >> 1) * 32;
    const int m0 = blockIdx.y * 128;
    const int n0 = blockIdx.x * 128;

    float c[4][4][4];
#pragma unroll
    for (int i = 0; i < 4; ++i)
#pragma unroll
        for (int j = 0; j < 4; ++j)
#pragma unroll
            for (int r = 0; r < 4; ++r) c[i][j][r] = 0.f;

    auto issue = [&](int i, int st) {
        const int k0 = i * 32;
        const uint32_t sb = smb + st * GSTAGE;
#pragma unroll
        for (int t = 0; t < 2; ++t) {
            int idx = t * 256 + tid;
            int row = idx >> 2, sub = idx & 3;
            uint32_t off = (uint32_t)(row * TSTRIDE + sub * 8) * 2;
            size_t ga = (size_t)(m0 + row) * D_ + k0 + sub * 8;
            size_t gb = (size_t)(n0 + row) * D_ + k0 + sub * 8;
            CP_ASYNC16(sb + off,         Ah + ga);
            CP_ASYNC16(sb + 10240 + off, Al + ga);
            CP_ASYNC16(sb + 20480 + off, Bh + gb);
            CP_ASYNC16(sb + 30720 + off, Bl + gb);
        }
    };

    const int arow = lane & 15, acol = (lane >> 4) << 3;
    const int brow = lane & 7,  bcol = ((lane >> 3) & 1) << 3;

    issue(0, 0); CP_COMMIT();
    issue(1, 1); CP_COMMIT();

    for (int i = 0; i < 32; ++i) {
        if (i < 31) CP_WAIT1(); else CP_WAIT0();
        __syncthreads();
        const uint32_t aB = smb + (i & 1) * GSTAGE;

#pragma unroll
        for (int ks = 0; ks < 2; ++ks) {
            const int kk = ks * 16;
            uint32_t ah[4][4], al[4][4];
#pragma unroll
            for (int mt = 0; mt < 4; ++mt) {
                uint32_t off = (uint32_t)((wm + mt * 16 + arow) * TSTRIDE + kk + acol) * 2;
                ldm_x4(ah[mt], aB + off);
                ldm_x4(al[mt], aB + 10240 + off);
            }
#pragma unroll
            for (int nt = 0; nt < 4; ++nt) {
                uint32_t boff = (uint32_t)((wn + nt * 8 + brow) * TSTRIDE + kk + bcol) * 2;
                uint32_t bh[2], bl[2];
                ldm_x2(bh, aB + 20480 + boff);
                ldm_x2(bl, aB + 30720 + boff);
#pragma unroll
                for (int mt = 0; mt < 4; ++mt) {
                    mma16816(c[mt][nt], ah[mt], bh);
                    mma16816(c[mt][nt], ah[mt], bl);
                    mma16816(c[mt][nt], al[mt], bh);
                }
            }
        }
        __syncthreads();
        if (i + 2 < 32) { issue(i + 2, i & 1); CP_COMMIT(); }
    }

    const int rl = lane >> 2;
    const int cl = (lane & 3) * 2;
#pragma unroll
    for (int mt = 0; mt < 4; ++mt) {
#pragma unroll
        for (int half = 0; half < 2; ++half) {
            int m = m0 + wm + mt * 16 + rl + half * 8;
#pragma unroll
            for (int nt = 0; nt < 4; ++nt) {
                int n = n0 + wn + nt * 8 + cl;
                float v0 = c[mt][nt][half * 2 + 0] + bias[n];
                float v1 = c[mt][nt][half * 2 + 1] + bias[n + 1];
                *(float2*)(C + (size_t)m * D_ + n) = make_float2(v0, v1);
            }
        }
    }
}

// ============================================================================
// Saliency Conv1d(D->H, k=3, pad=1): sal[b,h,l]
// ============================================================================
#define CONV_SMEM (18 * 1028 * 4)
__global__ void __launch_bounds__(256) conv_sal_kernel(
    const float* __restrict__ src, const float* __restrict__ cw,
    const float* __restrict__ cb, float* __restrict__ sal)
{
    extern __shared__ float ss[];
    const int bid = blockIdx.x;
    const int b = bid >> 7, lt = bid & 127;
    const int l0 = lt * 16;
    const int tid = threadIdx.x;

#pragma unroll
    for (int it = 0; it < 18; ++it) {
        int idx = it * 256 + tid;
        int row = idx >> 8;
        int c4 = idx & 255;
        int gl = l0 + row - 1;
        float4 v = make_float4(0.f, 0.f, 0.f, 0.f);
        if (gl >= 0 && gl < L_)
            v = *(const float4*)(src + ((size_t)b * L_ + gl) * D_ + c4 * 4);
        *(float4*)(ss + row * 1028 + c4 * 4) = v;
    }
    __syncthreads();

    const int h = tid >> 4, li = tid & 15;
    const float* wp = cw + (size_t)h * D_ * 3;
    float acc = 0.f;
#pragma unroll 4
    for (int d = 0; d < D_; ++d) {
        float w0 = wp[d * 3 + 0], w1 = wp[d * 3 + 1], w2 = wp[d * 3 + 2];
        acc = fmaf(ss[(li + 0) * 1028 + d], w0, acc);
        acc = fmaf(ss[(li + 1) * 1028 + d], w1, acc);
        acc = fmaf(ss[(li + 2) * 1028 + d], w2, acc);
    }
    sal[(size_t)(b * H_ + h) * L_ + l0 + li] = acc + cb[h];
}

// ============================================================================
// Fused PURE-FP16 tensor-core attention (R14 structure) + 2 CTAs/SM.
// ============================================================================
#define PH_PITCH 2056
#define KV_OFF  65792
#define V_STG   18432
#define SL_WARP 2304
#define SL_STG  1152
#define RED_OFF 65792
#define Q_OFF   102656
#define SUM_OFF 104960
#define INV_OFF 105984
#define ATTN_SMEM 106048
#define LN32 3.4657359027997265f

__global__ void __launch_bounds__(512, 2) attn_kernel(
    const __half* __restrict__ Qf, const __half* __restrict__ Kf,
    const __half* __restrict__ Vf,
    const float* __restrict__ sal,
    __nv_bfloat16* __restrict__ ctxh, __nv_bfloat16* __restrict__ ctxl,
    float* __restrict__ attn)
{
    extern __shared__ __align__(128) char smem[];
    __half* sP  = (__half*)smem;
    float* sSum = (float*)(smem + SUM_OFF);
    float* sInv = (float*)(smem + INV_OFF);
    const uint32_t smb = smem_u32(smem);
    const uint32_t pB = smb;

    const int tid = threadIdx.x;
    const int wid = tid >> 5;
    const int lane = tid & 31;
    const int q0 = blockIdx.x * 16;
    const int bh = blockIdx.y;
    const size_t base = (size_t)bh * (L_ * DH_);
    const float* salRow = sal + (size_t)bh * L_;
    const uint32_t wsl = smb + KV_OFF + wid * SL_WARP;

    // stage Q tile (16 rows x 64 fp16, pitch 72)
    if (tid < 128) {
        int r = tid >> 3, s = tid & 7;
        const uint4* gq = (const uint4*)(Qf + base + (size_t)q0 * DH_);
        *(uint4*)((__half*)(smem + Q_OFF) + r * 72 + s * 8) = gq[tid];
    }
    __syncthreads();

    const int arow = lane & 15, acol = (lane >> 4) << 3;
    const int brow = lane & 7;
    const uint32_t bcol16 = ((lane >> 3) & 1) << 4;
    uint32_t fQ[4][4];
    {
        const uint32_t qB = smb + Q_OFF;
#pragma unroll
        for (int ks = 0; ks < 4; ++ks)
            ldm_x4(fQ[ks], qB + (uint32_t)(arow * 72 + ks * 16 + acol) * 2);
    }

    auto issueK = [&](int kt, int st) {
        const uint32_t sb = wsl + st * SL_STG;
        const size_t gk = base + (size_t)(kt * 128 + wid * 8) * DH_;
#pragma unroll
        for (int j = 0; j < 2; ++j) {
            int id = lane + 32 * j;
            int row = id >> 3, seg = id & 7;
            CP_ASYNC16(sb + (uint32_t)(row * 144 + seg * 16),
                       Kf + gk + (size_t)row * DH_ + seg * 8);
        }
    };
    auto issueV = [&](int t128, int st) {
        const uint32_t sb = smb + KV_OFF + st * V_STG;
        const __half* pv = Vf + base + (size_t)t128 * 128 * DH_;
#pragma unroll
        for (int t = 0; t < 2; ++t) {
            int idx = t * 512 + tid;
            int r = idx >> 3, s = idx & 7;
            CP_ASYNC16(sb + (uint32_t)(r * 144 + s * 16),
                       pv + (size_t)r * DH_ + s * 8);
        }
    };

    // ---- Phase 1: per-warp streaming, fp16, barrier-free ----
    issueK(0, 0); CP_COMMIT();
    issueK(1, 1); CP_COMMIT();

    float sum_lo = 0.f, sum_hi = 0.f;
    const int row4 = lane >> 2;
    const int colw = wid * 8 + (lane & 3) * 2;
    float2 salc = *(const float2*)(salRow + colw);
    for (int kt = 0; kt < 16; ++kt) {
        if (kt < 15) CP_WAIT1(); else CP_WAIT0();
        __syncwarp();
        const uint32_t kb = wsl + (kt & 1) * SL_STG;

        float c[4] = {0.f, 0.f, 0.f, 0.f};
        uint32_t bo = kb + (uint32_t)(brow * 144) + bcol16;
#pragma unroll
        for (int ks = 0; ks < 4; ++ks) {
            uint32_t kf[2];
            ldm_x2(kf, bo + ks * 32);
            mma16816h(c, fQ[ks], kf);
        }
        if (kt + 2 < 16) { issueK(kt + 2, kt & 1); CP_COMMIT(); }

        float2 saln;
        if (kt < 15) saln = *(const float2*)(salRow + (kt + 1) * 128 + colw);

        float e0 = __expf(fmaf(c[0], 0.125f, salc.x) + LN32);
        float e1 = __expf(fmaf(c[1], 0.125f, salc.y) + LN32);
        float e2 = __expf(fmaf(c[2], 0.125f, salc.x) + LN32);
        float e3 = __expf(fmaf(c[3], 0.125f, salc.y) + LN32);
        int col = kt * 128 + colw;
        *(__half2*)(sP + row4 * PH_PITCH + col) =
            __halves2half2(__float2half(e0), __float2half(e1));
        *(__half2*)(sP + (row4 + 8) * PH_PITCH + col) =
            __halves2half2(__float2half(e2), __float2half(e3));
        sum_lo += e0 + e1;
        sum_hi += e2 + e3;
        salc = saln;
    }

    // ---- row-sum reduction ----
    sum_lo += __shfl_xor_sync(0xffffffffu, sum_lo, 1);
    sum_lo += __shfl_xor_sync(0xffffffffu, sum_lo, 2);
    sum_hi += __shfl_xor_sync(0xffffffffu, sum_hi, 1);
    sum_hi += __shfl_xor_sync(0xffffffffu, sum_hi, 2);
    if ((lane & 3) == 0) {
        sSum[row4 * 16 + wid] = sum_lo;
        sSum[(row4 + 8) * 16 + wid] = sum_hi;
    }
    __syncthreads();

    issueV(0, 0); CP_COMMIT();
    issueV(1, 1); CP_COMMIT();

    if (tid < 16) {
        float s = 0.f;
#pragma unroll
        for (int j = 0; j < 16; ++j) s += sSum[tid * 16 + j];
        sInv[tid] = 1.f / s;
    }
    __syncthreads();

    // ---- Phase 2: attn write + 1-term fp16 PV ----
    const int n8p = wid & 7;
    const int kh = wid >> 3;
    float cc[4] = {0.f, 0.f, 0.f, 0.f};

    for (int lt = 0; lt < 16; ++lt) {
        if (lt < 15) CP_WAIT1(); else CP_WAIT0();
        __syncthreads();

        {
            int row = wid;
            float inv = sInv[row];
            int c0 = lt * 128 + lane * 4;
            __half2 a0 = *(const __half2*)(sP + row * PH_PITCH + c0);
            __half2 a1 = *(const __half2*)(sP + row * PH_PITCH + c0 + 2);
            float4 v;
            v.x = __half2float(a0.x) * inv;
            v.y = __half2float(a0.y) * inv;
            v.z = __half2float(a1.x) * inv;
            v.w = __half2float(a1.y) * inv;
            *(float4*)(attn + ((size_t)bh * L_ + q0 + row) * L_ + c0) = v;
        }

        const uint32_t vb = smb + KV_OFF + (lt & 1) * V_STG;
#pragma unroll
        for (int ksl = 0; ksl < 4; ++ksl) {
            int ks = kh * 4 + ksl;
            int kp = lt * 128 + ks * 16;
            uint32_t fA[4];
            ldm_x4(fA, pB + (uint32_t)(arow * PH_PITCH + kp + acol) * 2);
            uint32_t fV[2];
            ldm_x2_t(fV, vb + (uint32_t)((ks * 16 + (lane & 15)) * 144 + n8p * 16));
            mma16816h(cc, fA, fV);
        }
        __syncthreads();
        if (lt + 2 < 16) { issueV(lt + 2, lt & 1); CP_COMMIT(); }
    }

    // ---- reduce ctx partials, write split bf16 ----
    float* red = (float*)(smem + RED_OFF);
    *(float4*)(red + wid * 128 + lane * 4) = make_float4(cc[0], cc[1], cc[2], cc[3]);
    __syncthreads();
    if (wid < 8) {
        float4 p = *(const float4*)(red + wid * 128 + lane * 4);
        float4 q = *(const float4*)(red + (wid + 8) * 128 + lane * 4);
        float v[4] = {p.x + q.x, p.y + q.y, p.z + q.z, p.w + q.w};
        int row = lane >> 2;
        int colp = (lane & 3) * 2;
        int b = bh >> 4, h = bh & 15;
        int n = h * 64 + wid * 8 + colp;
#pragma unroll
        for (int half = 0; half < 2; ++half) {
            int r = row + half * 8;
            float inv = sInv[r];
            int m = b * 2048 + q0 + r;
            float v0 = v[half * 2 + 0] * inv, v1 = v[half * 2 + 1] * inv;
            __nv_bfloat16 h0 = __float2bfloat16(v0);
            __nv_bfloat16 h1 = __float2bfloat16(v1);
            *(__nv_bfloat162*)(ctxh + (size_t)m * D_ + n) = __nv_bfloat162(h0, h1);
            *(__nv_bfloat162*)(ctxl + (size_t)m * D_ + n) = __nv_bfloat162(
                __float2bfloat16(v0 - __bfloat162float(h0)),
                __float2bfloat16(v1 - __bfloat162float(h1)));
        }
    }
}

// ============================================================================
// host launcher
// ============================================================================
extern "C" void kernel_launch(void* const* d_in, const int* in_sizes, int n_in,
                              void* d_out, int out_size)
{
    const float* src = (const float*)d_in[0];
    const float* Wq  = (const float*)d_in[1];
    const float* bq  = (const float*)d_in[2];
    const float* Wk  = (const float*)d_in[3];
    const float* bk  = (const float*)d_in[4];
    const float* Wv  = (const float*)d_in[5];
    const float* bv  = (const float*)d_in[6];
    const float* Wo  = (const float*)d_in[7];
    const float* bo  = (const float*)d_in[8];
    const float* cw  = (const float*)d_in[9];
    const float* cb  = (const float*)d_in[10];

    float* out      = (float*)d_out;
    float* attn_out = out + OUT_ELEMS;

    float* salp;
    __half *Af, *Whf, *Wlf, *Qf, *Kf, *Vf;
    __nv_bfloat16 *Ahi, *Alo, *Whi, *Wlo;
    cudaGetSymbolAddress((void**)&salp, g_sal);
    cudaGetSymbolAddress((void**)&Af,   g_Af);
    cudaGetSymbolAddress((void**)&Whf,  g_Whf);
    cudaGetSymbolAddress((void**)&Wlf,  g_Wlf);
    cudaGetSymbolAddress((void**)&Ahi,  g_Ahi);
    cudaGetSymbolAddress((void**)&Alo,  g_Alo);
    cudaGetSymbolAddress((void**)&Whi,  g_Whi);
    cudaGetSymbolAddress((void**)&Wlo,  g_Wlo);
    cudaGetSymbolAddress((void**)&Qf,   g_Qf);
    cudaGetSymbolAddress((void**)&Kf,   g_Kf);
    cudaGetSymbolAddress((void**)&Vf,   g_Vf);

    cudaFuncSetAttribute(conv_sal_kernel,
        cudaFuncAttributeMaxDynamicSharedMemorySize, CONV_SMEM);
    cudaFuncSetAttribute(attn_kernel,
        cudaFuncAttributeMaxDynamicSharedMemorySize, ATTN_SMEM);
    cudaFuncSetAttribute(mma_gemm_f16x2,
        cudaFuncAttributeMaxDynamicSharedMemorySize, GEMM2_SMEM);
    cudaFuncSetAttribute(mma_gemm_bf16x3,
        cudaFuncAttributeMaxDynamicSharedMemorySize, GEMM_SMEM);

    // saliency conv
    conv_sal_kernel<<<B_ * 128, 256, CONV_SMEM>>>(src, cw, cb, salp);

    // conversions: src -> fp16; weights -> fp16 pairs (QKV) / bf16 pair (Wo)
    cvt_src_f16<<<(M_ * D_ / 4 + 255) / 256, 256>>>(src, Af, M_ * D_ / 4);
    dim3 wgrid(D_ * D_ / 4 / 256, 4);
    cvt_w_mixed<<<wgrid, 256>>>(Wq, Wk, Wv, Wo, Whf, Wlf, Whi, Wlo);

    // Q, K, V projections (fp16x2) in one launch
    dim3 qkvgrid(8, 32, 3);
    mma_gemm_f16x2<<<qkvgrid, 256, GEMM2_SMEM>>>(Af, Whf, Wlf,
        bq, bk, bv, Qf, Kf, Vf);

    // fused fp16 tensor-core attention (writes attn + ctx split into Ahi/Alo)
    dim3 agrid(L_ / 16, B_ * H_);
    attn_kernel<<<agrid, 512, ATTN_SMEM>>>(Qf, Kf, Vf, salp,
                                           Ahi, Alo, attn_out);

    // output projection (bf16x3, Wo = slice 3) -> d_out
    dim3 ogrid(8, 32);
    mma_gemm_bf16x3<<<ogrid, 256, GEMM_SMEM>>>(Ahi, Alo,
        Whi + 3 * (size_t)D_ * D_, Wlo + 3 * (size_t)D_ * D_, bo, out);
}